// round 11
// baseline (speedup 1.0000x reference)
#include <cuda_runtime.h>
#include <cuda_bf16.h>
#include <cstddef>

#define MAXC   16     // max combos (2*T*B <= 12 here)
#define MAXPB  64     // max point-blocks per combo / extras row

__device__ float g_nd2_part[MAXC * MAXPB];
__device__ float g_opp_part[MAXC * MAXPB];
__device__ float g_occ_part[2 * MAXPB];
__device__ float g_sf_part [2 * MAXPB];
__device__ unsigned int g_ctr;   // zero-init; wraps each launch -> replay-safe

// acq_rel wrap-increment: release orders this thread's prior stores; acquire
// makes all contributors' stores visible to the winner. No CCTL.IVALL.
__device__ __forceinline__ unsigned int atomicInc_acqrel(unsigned int* p,
                                                         unsigned int wrap) {
    unsigned int old;
    asm volatile("atom.acq_rel.gpu.inc.u32 %0, [%1], %2;"
                 : "=r"(old) : "l"(p), "r"(wrap) : "memory");
    return old;
}

// ---- packed f32x2 helpers (sm_103a FFMA2 path, PTX-only) ----
__device__ __forceinline__ unsigned long long pack2(float lo, float hi) {
    unsigned long long r;
    asm("mov.b64 %0, {%1, %2};" : "=l"(r) : "f"(lo), "f"(hi));
    return r;
}
__device__ __forceinline__ void unpack2(unsigned long long v, float& lo, float& hi) {
    asm("mov.b64 {%0, %1}, %2;" : "=f"(lo), "=f"(hi) : "l"(v));
}
__device__ __forceinline__ unsigned long long fma2(unsigned long long a,
                                                   unsigned long long b,
                                                   unsigned long long c) {
    unsigned long long d;
    asm("fma.rn.f32x2 %0, %1, %2, %3;" : "=l"(d) : "l"(a), "l"(b), "l"(c));
    return d;
}
__device__ __forceinline__ unsigned long long mul2(unsigned long long a,
                                                   unsigned long long b) {
    unsigned long long d;
    asm("mul.rn.f32x2 %0, %1, %2;" : "=l"(d) : "l"(a), "l"(b));
    return d;
}

__device__ __forceinline__ void block_reduce2(float& a, float& b,
                                              float* sA, float* sB) {
    const int lane = threadIdx.x & 31;
    const int wid  = threadIdx.x >> 5;
    #pragma unroll
    for (int off = 16; off > 0; off >>= 1) {
        a += __shfl_down_sync(0xffffffffu, a, off);
        b += __shfl_down_sync(0xffffffffu, b, off);
    }
    if (lane == 0) { sA[wid] = a; sB[wid] = b; }
    __syncthreads();
    if (threadIdx.x == 0) {
        const int nw = (blockDim.x + 31) >> 5;
        float ra = 0.f, rb = 0.f;
        for (int w = 0; w < nw; w++) { ra += sA[w]; rb += sB[w]; }
        a = ra; b = rb;
    }
}

// ---------------------------------------------------------------------------
// Single kernel, no cross-block NN state.
// KNN rows (combo < KC): 64 threads/block, ONE source point per thread, FULL
//   target scan against all N targets staged in SMEM. Complete min (+argmin
//   and opposite-flow gather for t==0) stays in registers. Block partial sums
//   go straight to globals.
// Extras rows: occlusion + static-flow partials.
// Last-arriving block (acq_rel wrap counter) folds partials + trafo -> out.
// ---------------------------------------------------------------------------
__global__ void __launch_bounds__(64) fused_kernel(
    const float* __restrict__ pc0, const float* __restrict__ pc1,
    const float* __restrict__ ffw, const float* __restrict__ fbw,
    const float* __restrict__ dfw, const float* __restrict__ dbw,
    const float* __restrict__ trfw, const float* __restrict__ trbw,
    const float* __restrict__ stfw, const float* __restrict__ stbw,
    float* __restrict__ out, int B, int N, int T)
{
    const int KC = 2 * T * B;
    const int combo = blockIdx.y;
    const int PB = gridDim.x;                 // point-blocks per combo
    extern __shared__ unsigned long long smU[];
    float4* sm4 = reinterpret_cast<float4*>(smU);
    __shared__ float sA[4], sB[4];
    __shared__ bool sFlag;
    const int tid = threadIdx.x;

    if (combo < KC) {
        const int b   = combo % B;
        const int t   = (combo / B) % T;
        const int dir = combo / (B * T);

        const float* src_pc = (dir == 0) ? pc0 : pc1;
        const float* tgt_pc = (dir == 0) ? pc1 : pc0;
        const float* src_fl = (dir == 0) ? ffw : fbw;
        const float* tgt_fl = (dir == 0) ? fbw : ffw;
        src_pc += (size_t)b * N * 3;
        tgt_pc += (size_t)b * N * 3;
        src_fl += ((size_t)t * B + b) * (size_t)N * 3;
        tgt_fl += ((size_t)t * B + b) * (size_t)N * 3;

        const int n = blockIdx.x * 64 + tid;
        const bool valid = (n < N);

        float wx = 0.f, wy = 0.f, wz = 0.f, w2 = 0.f;
        float sfx = 0.f, sfy = 0.f, sfz = 0.f;
        if (valid) {
            sfx = src_fl[n * 3 + 0]; sfy = src_fl[n * 3 + 1]; sfz = src_fl[n * 3 + 2];
            wx = src_pc[n * 3 + 0] + sfx;
            wy = src_pc[n * 3 + 1] + sfy;
            wz = src_pc[n * 3 + 2] + sfz;
            w2 = fmaf(wx, wx, fmaf(wy, wy, wz * wz));
        }

        float v_nd2 = 0.f, v_opp = 0.f;

        if (t == 0) {
            // ---------- scalar argmin path ----------
            for (int i = tid; i < N; i += 64) {
                const float ax = tgt_pc[i * 3 + 0];
                const float ay = tgt_pc[i * 3 + 1];
                const float az = tgt_pc[i * 3 + 2];
                sm4[i] = make_float4(ax, ay, az, fmaf(ax, ax, fmaf(ay, ay, az * az)));
            }
            __syncthreads();

            float best = 3.402823466e+38f;
            int   bi = 0;
            #pragma unroll 4
            for (int j = 0; j < N; j++) {
                const float4 a = sm4[j];
                const float s = fmaf(fmaf(a.x, wx, fmaf(a.y, wy, a.z * wz)), -2.f, a.w);
                if (s < best) { best = s; bi = j; }
            }
            if (valid) {
                v_nd2 = fmaxf(best + w2, 0.f);
                const float ox = sfx + tgt_fl[bi * 3 + 0];
                const float oy = sfy + tgt_fl[bi * 3 + 1];
                const float oz = sfz + tgt_fl[bi * 3 + 2];
                v_opp = fmaf(ox, ox, fmaf(oy, oy, oz * oz));
            }
        } else {
            // ---------- packed f32x2 min-only path ----------
            const int cnt2 = (N + 1) >> 1;
            for (int i = tid; i < cnt2; i += 64) {
                const int ta = 2 * i;
                const int tb = ta + 1;
                const float ax0 = tgt_pc[ta * 3 + 0];
                const float ay0 = tgt_pc[ta * 3 + 1];
                const float az0 = tgt_pc[ta * 3 + 2];
                const float aw0 = fmaf(ax0, ax0, fmaf(ay0, ay0, az0 * az0));
                float ax1 = 0.f, ay1 = 0.f, az1 = 0.f, aw1 = 3.402823466e+38f;
                if (tb < N) {
                    ax1 = tgt_pc[tb * 3 + 0];
                    ay1 = tgt_pc[tb * 3 + 1];
                    az1 = tgt_pc[tb * 3 + 2];
                    aw1 = fmaf(ax1, ax1, fmaf(ay1, ay1, az1 * az1));
                }
                smU[i * 4 + 0] = pack2(ax0, ax1);
                smU[i * 4 + 1] = pack2(ay0, ay1);
                smU[i * 4 + 2] = pack2(az0, az1);
                smU[i * 4 + 3] = pack2(aw0, aw1);
            }
            __syncthreads();

            const unsigned long long X = pack2(wx, wx), Y = pack2(wy, wy), Z = pack2(wz, wz);
            const unsigned long long NEG2 = pack2(-2.f, -2.f);

            float bE = 3.402823466e+38f, bO = 3.402823466e+38f;
            #pragma unroll 8
            for (int j2 = 0; j2 < cnt2; j2++) {
                const ulonglong2 pxy = *reinterpret_cast<const ulonglong2*>(&smU[j2 * 4]);
                const ulonglong2 pzw = *reinterpret_cast<const ulonglong2*>(&smU[j2 * 4 + 2]);
                const unsigned long long s =
                    fma2(fma2(pxy.x, X, fma2(pxy.y, Y, mul2(pzw.x, Z))), NEG2, pzw.y);
                float lo, hi; unpack2(s, lo, hi);
                bE = fminf(bE, lo); bO = fminf(bO, hi);
            }
            if (valid) v_nd2 = fmaxf(fminf(bE, bO) + w2, 0.f);
        }

        block_reduce2(v_nd2, v_opp, sA, sB);
        if (tid == 0) {
            __stcg(&g_nd2_part[combo * PB + blockIdx.x], v_nd2);
            __stcg(&g_opp_part[combo * PB + blockIdx.x], v_opp);
        }
    } else {
        // ---- extras: occlusion + static-flow partials ----
        const int dir = combo - KC;
        const float* pc  = (dir == 0) ? pc0  : pc1;
        const float* fl  = (dir == 0) ? ffw  : fbw;
        const float* dis = (dir == 0) ? dfw  : dbw;
        const float* st  = (dir == 0) ? stfw : stbw;
        const float* trg = (dir == 0) ? trfw : trbw;
        const int BN = B * N;
        fl += (size_t)2 * BN * 3;

        float occ = 0.f, sf = 0.f;
        for (int i = blockIdx.x * 64 + tid; i < BN; i += PB * 64) {
            occ += dis[i];
            const int b = i / N;
            const float* m = trg + (size_t)b * 16;
            const float px = pc[i * 3 + 0], py = pc[i * 3 + 1], pz = pc[i * 3 + 2];
            const float ix = fmaf(m[0], px, fmaf(m[1],  py, fmaf(m[2],  pz, m[3])))  - px;
            const float iy = fmaf(m[4], px, fmaf(m[5],  py, fmaf(m[6],  pz, m[7])))  - py;
            const float iz = fmaf(m[8], px, fmaf(m[9],  py, fmaf(m[10], pz, m[11]))) - pz;
            const float* f = fl + (size_t)i * 3;
            const float dx = f[0] - ix, dy = f[1] - iy, dz = f[2] - iz;
            sf += st[i] * fmaf(dx, dx, fmaf(dy, dy, dz * dz));
        }
        block_reduce2(occ, sf, sA, sB);
        if (tid == 0) {
            __stcg(&g_occ_part[dir * PB + blockIdx.x], occ);
            __stcg(&g_sf_part [dir * PB + blockIdx.x], sf);
        }
    }

    // ---- last-arriving block folds everything -> out[0] ----
    if (tid == 0) {
        const unsigned total = gridDim.x * gridDim.y;
        const unsigned old = atomicInc_acqrel(&g_ctr, total - 1);
        sFlag = (old == total - 1);
    }
    __syncthreads();
    if (!sFlag) return;

    const int BN = B * N;
    float accA = 0.f, accB = 0.f;
    for (int i = tid; i < KC * PB; i += 64) {
        const int c  = i / PB;
        const int tt = (c / B) % T;
        const float wnd = (tt == 0) ? 0.5f : 0.25f;   // knn pens * 0.5 fw/bw avg
        float v = wnd * __ldcg(&g_nd2_part[i]);
        if (tt == 0) v += 0.5f * __ldcg(&g_opp_part[i]);
        accA += v;
    }
    for (int i = tid; i < 2 * PB; i += 64) {
        accA += 0.05f * __ldcg(&g_occ_part[i]) + 0.5f * __ldcg(&g_sf_part[i]);
    }
    for (int e = tid; e < B * 16; e += 64) {
        const int bbq = e >> 4, r = (e >> 2) & 3, k = e & 3;
        const float* A  = trfw + (size_t)bbq * 16;
        const float* Bm = trbw + (size_t)bbq * 16;
        float c = 0.f;
        #pragma unroll
        for (int j = 0; j < 4; j++) c = fmaf(A[r * 4 + j], Bm[j * 4 + k], c);
        const float d = c - ((r == k) ? 1.f : 0.f);
        accB += d * d;
    }
    __syncthreads();
    block_reduce2(accA, accB, sA, sB);
    if (tid == 0) out[0] = accA / (float)BN + accB / (float)B;
}

extern "C" void kernel_launch(void* const* d_in, const int* in_sizes, int n_in,
                              void* d_out, int out_size)
{
    const float* pc0  = (const float*)d_in[0];
    const float* pc1  = (const float*)d_in[1];
    const float* ffw  = (const float*)d_in[2];
    const float* fbw  = (const float*)d_in[3];
    const float* dfw  = (const float*)d_in[4];
    const float* dbw  = (const float*)d_in[5];
    const float* trfw = (const float*)d_in[6];
    const float* trbw = (const float*)d_in[7];
    const float* stfw = (const float*)d_in[8];
    const float* stbw = (const float*)d_in[9];
    float* out = (float*)d_out;

    const int B = in_sizes[6] / 16;                 // trafo_fw = [B,4,4]
    const int N = in_sizes[0] / (3 * B);            // pc0 = [B,N,3]
    const int T = in_sizes[2] / (3 * B * N);        // flows_fw = [T,B,N,3]

    const int KC = 2 * T * B;
    const int PB = (N + 63) / 64;                   // 64 source points / block

    dim3 grid(PB, KC + 2);
    const size_t smem = (size_t)((N + 1) / 2) * 32; // 32KB at N=2048 (both views)

    fused_kernel<<<grid, 64, smem>>>(pc0, pc1, ffw, fbw, dfw, dbw,
                                     trfw, trbw, stfw, stbw, out, B, N, T);
}

// round 13
// speedup vs baseline: 2.4698x; 2.4698x over previous
#include <cuda_runtime.h>
#include <cuda_bf16.h>
#include <cstddef>

#define MAXC   16     // max combos (2*T*B <= 12 here)
#define JSPLIT 16     // target-dimension split
#define MAXN   4096   // max points
#define MAXP   256    // max partial blocks per row

// Packed per-point winner: ~(((u64)mono(d2) << 32) | idx), folded with
// atomicMax (no-return -> REDG). 0 = "empty"; combine reads + resets to 0.
__device__ unsigned long long g_slot[MAXC * MAXN];
__device__ float g_nd2_part[MAXC * 32];
__device__ float g_opp_part[MAXC * 32];
__device__ float g_occ_part[2 * MAXP];
__device__ float g_sf_part [2 * MAXP];
__device__ unsigned int g_ctr;                   // zero-init; wraps each launch

__device__ __forceinline__ unsigned int fkey(float f) {
    const unsigned int u = __float_as_uint(f);
    return u ^ ((u & 0x80000000u) ? 0xFFFFFFFFu : 0x80000000u);
}
__device__ __forceinline__ float fkey_inv(unsigned int k) {
    const unsigned int u = (k & 0x80000000u) ? (k ^ 0x80000000u) : ~k;
    return __uint_as_float(u);
}

// ---- packed f32x2 helpers (sm_103a FFMA2 path, PTX-only) ----
__device__ __forceinline__ unsigned long long pack2(float lo, float hi) {
    unsigned long long r;
    asm("mov.b64 %0, {%1, %2};" : "=l"(r) : "f"(lo), "f"(hi));
    return r;
}
__device__ __forceinline__ void unpack2(unsigned long long v, float& lo, float& hi) {
    asm("mov.b64 {%0, %1}, %2;" : "=f"(lo), "=f"(hi) : "l"(v));
}
__device__ __forceinline__ unsigned long long fma2(unsigned long long a,
                                                   unsigned long long b,
                                                   unsigned long long c) {
    unsigned long long d;
    asm("fma.rn.f32x2 %0, %1, %2, %3;" : "=l"(d) : "l"(a), "l"(b), "l"(c));
    return d;
}
__device__ __forceinline__ unsigned long long mul2(unsigned long long a,
                                                   unsigned long long b) {
    unsigned long long d;
    asm("mul.rn.f32x2 %0, %1, %2;" : "=l"(d) : "l"(a), "l"(b));
    return d;
}

__device__ __forceinline__ void block_reduce2(float& a, float& b,
                                              float* sA, float* sB) {
    const int lane = threadIdx.x & 31;
    const int wid  = threadIdx.x >> 5;
    #pragma unroll
    for (int off = 16; off > 0; off >>= 1) {
        a += __shfl_down_sync(0xffffffffu, a, off);
        b += __shfl_down_sync(0xffffffffu, b, off);
    }
    if (lane == 0) { sA[wid] = a; sB[wid] = b; }
    __syncthreads();
    if (threadIdx.x == 0) {
        const int nw = (blockDim.x + 31) >> 5;
        float ra = 0.f, rb = 0.f;
        for (int w = 0; w < nw; w++) { ra += sA[w]; rb += sB[w]; }
        a = ra; b = rb;
    }
}

// ---------------------------------------------------------------------------
// Pass 1: per-(combo, 256-pt block, 128-target chunk) partial NN folded into
// packed-key atomicMax. t==0 scalar argmin; t!=0 packed f32x2 FMA over target
// pairs, even/odd scalar min accumulators. Extras rows: occlusion +
// static-flow partial sums.
// ---------------------------------------------------------------------------
__global__ void __launch_bounds__(128) chunk_kernel(
    const float* __restrict__ pc0, const float* __restrict__ pc1,
    const float* __restrict__ ffw, const float* __restrict__ fbw,
    const float* __restrict__ dfw, const float* __restrict__ dbw,
    const float* __restrict__ trfw, const float* __restrict__ trbw,
    const float* __restrict__ stfw, const float* __restrict__ stbw,
    int B, int N, int T)
{
    const int KC = 2 * T * B;
    const int combo = blockIdx.y;
    extern __shared__ unsigned long long smU[];
    float4* sm4 = reinterpret_cast<float4*>(smU);
    __shared__ float sA[8], sB[8];

    if (combo < KC) {
        const int b   = combo % B;
        const int t   = (combo / B) % T;
        const int dir = combo / (B * T);
        const int chunk = (N + JSPLIT - 1) / JSPLIT;
        const int xb = blockIdx.x / JSPLIT;
        const int jc = blockIdx.x % JSPLIT;
        const int j0 = jc * chunk;
        const int cnt = min(chunk, N - j0);
        if (cnt <= 0) return;

        const float* src_pc = (dir == 0) ? pc0 : pc1;
        const float* tgt_pc = (dir == 0) ? pc1 : pc0;
        const float* src_fl = (dir == 0) ? ffw : fbw;
        src_pc += (size_t)b * N * 3;
        tgt_pc += (size_t)b * N * 3;
        src_fl += ((size_t)t * B + b) * (size_t)N * 3;

        const int n0 = xb * 256 + (int)threadIdx.x;
        const int n1 = n0 + 128;
        const bool v0 = (n0 < N);
        const bool v1 = (n1 < N);

        float w0x = 0.f, w0y = 0.f, w0z = 0.f, w20 = 0.f;
        float w1x = 0.f, w1y = 0.f, w1z = 0.f, w21 = 0.f;
        if (v0) {
            w0x = src_pc[n0 * 3 + 0] + src_fl[n0 * 3 + 0];
            w0y = src_pc[n0 * 3 + 1] + src_fl[n0 * 3 + 1];
            w0z = src_pc[n0 * 3 + 2] + src_fl[n0 * 3 + 2];
            w20 = fmaf(w0x, w0x, fmaf(w0y, w0y, w0z * w0z));
        }
        if (v1) {
            w1x = src_pc[n1 * 3 + 0] + src_fl[n1 * 3 + 0];
            w1y = src_pc[n1 * 3 + 1] + src_fl[n1 * 3 + 1];
            w1z = src_pc[n1 * 3 + 2] + src_fl[n1 * 3 + 2];
            w21 = fmaf(w1x, w1x, fmaf(w1y, w1y, w1z * w1z));
        }

        unsigned long long* slot = g_slot + (size_t)combo * N;

        if (t == 0) {
            // ---------- scalar argmin path ----------
            for (int i = threadIdx.x; i < cnt; i += 128) {
                const float ax = tgt_pc[(j0 + i) * 3 + 0];
                const float ay = tgt_pc[(j0 + i) * 3 + 1];
                const float az = tgt_pc[(j0 + i) * 3 + 2];
                sm4[i] = make_float4(ax, ay, az, fmaf(ax, ax, fmaf(ay, ay, az * az)));
            }
            __syncthreads();

            float best0 = 3.402823466e+38f, best1 = 3.402823466e+38f;
            int   bi0 = 0, bi1 = 0;
            #pragma unroll 4
            for (int j = 0; j < cnt; j++) {
                const float4 a = sm4[j];
                const float s0 = fmaf(fmaf(a.x, w0x, fmaf(a.y, w0y, a.z * w0z)), -2.f, a.w);
                if (s0 < best0) { best0 = s0; bi0 = j; }
                const float s1 = fmaf(fmaf(a.x, w1x, fmaf(a.y, w1y, a.z * w1z)), -2.f, a.w);
                if (s1 < best1) { best1 = s1; bi1 = j; }
            }
            if (v0) {
                const unsigned long long key =
                    ((unsigned long long)fkey(best0 + w20) << 32) | (unsigned int)(j0 + bi0);
                atomicMax(slot + n0, ~key);
            }
            if (v1) {
                const unsigned long long key =
                    ((unsigned long long)fkey(best1 + w21) << 32) | (unsigned int)(j0 + bi1);
                atomicMax(slot + n1, ~key);
            }
        } else {
            // ---------- packed f32x2 min-only path ----------
            const int cnt2 = (cnt + 1) >> 1;
            for (int i = threadIdx.x; i < cnt2; i += 128) {
                const int ta = j0 + 2 * i;
                const int tb = ta + 1;
                const float ax0 = tgt_pc[ta * 3 + 0];
                const float ay0 = tgt_pc[ta * 3 + 1];
                const float az0 = tgt_pc[ta * 3 + 2];
                const float aw0 = fmaf(ax0, ax0, fmaf(ay0, ay0, az0 * az0));
                float ax1 = 0.f, ay1 = 0.f, az1 = 0.f, aw1 = 3.402823466e+38f;
                if (tb < j0 + cnt) {
                    ax1 = tgt_pc[tb * 3 + 0];
                    ay1 = tgt_pc[tb * 3 + 1];
                    az1 = tgt_pc[tb * 3 + 2];
                    aw1 = fmaf(ax1, ax1, fmaf(ay1, ay1, az1 * az1));
                }
                smU[i * 4 + 0] = pack2(ax0, ax1);
                smU[i * 4 + 1] = pack2(ay0, ay1);
                smU[i * 4 + 2] = pack2(az0, az1);
                smU[i * 4 + 3] = pack2(aw0, aw1);
            }
            __syncthreads();

            const unsigned long long X0 = pack2(w0x, w0x), Y0 = pack2(w0y, w0y), Z0 = pack2(w0z, w0z);
            const unsigned long long X1 = pack2(w1x, w1x), Y1 = pack2(w1y, w1y), Z1 = pack2(w1z, w1z);
            const unsigned long long NEG2 = pack2(-2.f, -2.f);

            float bE0 = 3.402823466e+38f, bO0 = 3.402823466e+38f;
            float bE1 = 3.402823466e+38f, bO1 = 3.402823466e+38f;
            #pragma unroll 8
            for (int j2 = 0; j2 < cnt2; j2++) {
                const ulonglong2 pxy = *reinterpret_cast<const ulonglong2*>(&smU[j2 * 4]);
                const ulonglong2 pzw = *reinterpret_cast<const ulonglong2*>(&smU[j2 * 4 + 2]);
                unsigned long long s = fma2(fma2(pxy.x, X0, fma2(pxy.y, Y0, mul2(pzw.x, Z0))), NEG2, pzw.y);
                float lo, hi; unpack2(s, lo, hi);
                bE0 = fminf(bE0, lo); bO0 = fminf(bO0, hi);
                s = fma2(fma2(pxy.x, X1, fma2(pxy.y, Y1, mul2(pzw.x, Z1))), NEG2, pzw.y);
                unpack2(s, lo, hi);
                bE1 = fminf(bE1, lo); bO1 = fminf(bO1, hi);
            }
            const float best0 = fminf(bE0, bO0);
            const float best1 = fminf(bE1, bO1);
            if (v0) atomicMax(slot + n0, ~((unsigned long long)fkey(best0 + w20) << 32));
            if (v1) atomicMax(slot + n1, ~((unsigned long long)fkey(best1 + w21) << 32));
        }
    } else {
        // ---- extras: occlusion + static-flow partials ----
        const int dir = combo - KC;
        const float* pc  = (dir == 0) ? pc0  : pc1;
        const float* fl  = (dir == 0) ? ffw  : fbw;
        const float* dis = (dir == 0) ? dfw  : dbw;
        const float* st  = (dir == 0) ? stfw : stbw;
        const float* trg = (dir == 0) ? trfw : trbw;
        const int BN = B * N;
        fl += (size_t)2 * BN * 3;

        float occ = 0.f, sf = 0.f;
        for (int i = blockIdx.x * 128 + (int)threadIdx.x; i < BN;
             i += gridDim.x * 128) {
            occ += dis[i];
            const int b = i / N;
            const float* m = trg + (size_t)b * 16;
            const float px = pc[i * 3 + 0], py = pc[i * 3 + 1], pz = pc[i * 3 + 2];
            const float ix = fmaf(m[0], px, fmaf(m[1],  py, fmaf(m[2],  pz, m[3])))  - px;
            const float iy = fmaf(m[4], px, fmaf(m[5],  py, fmaf(m[6],  pz, m[7])))  - py;
            const float iz = fmaf(m[8], px, fmaf(m[9],  py, fmaf(m[10], pz, m[11]))) - pz;
            const float* f = fl + (size_t)i * 3;
            const float dx = f[0] - ix, dy = f[1] - iy, dz = f[2] - iz;
            sf += st[i] * fmaf(dx, dx, fmaf(dy, dy, dz * dz));
        }
        block_reduce2(occ, sf, sA, sB);
        if (threadIdx.x == 0) {
            g_occ_part[dir * gridDim.x + blockIdx.x] = occ;
            g_sf_part [dir * gridDim.x + blockIdx.x] = sf;
        }
    }
}

// ---------------------------------------------------------------------------
// Pass 2 (unchanged from R9): one thread per point. Decode packed winner
// (reset slot for next replay), opp gather for t==0, block-reduce; the
// last-arriving block folds partials + extras + trafo loss -> out[0].
// ---------------------------------------------------------------------------
__global__ void __launch_bounds__(256) combine_kernel(
    const float* __restrict__ ffw, const float* __restrict__ fbw,
    const float* __restrict__ trfw, const float* __restrict__ trbw,
    float* __restrict__ out, int B, int N, int T, int nbx1)
{
    const int combo = blockIdx.y;
    const int b   = combo % B;
    const int t   = (combo / B) % T;
    const int dir = combo / (B * T);
    const int KC  = 2 * T * B;
    const int tid = threadIdx.x;
    __shared__ float sA[8], sB[8];
    __shared__ bool isLast;

    const int n = blockIdx.x * 256 + tid;
    float v_nd2 = 0.f, v_opp = 0.f;
    if (n < N) {
        unsigned long long* slot = g_slot + (size_t)combo * N + n;
        const unsigned long long key = ~(*slot);
        *slot = 0ULL;                                   // reset for next replay
        const float d2 = fkey_inv((unsigned int)(key >> 32));
        v_nd2 = fmaxf(d2, 0.f);
        if (t == 0) {
            const int idx = (int)(unsigned int)(key & 0xFFFFFFFFu);
            const float* src_fl = ((dir == 0) ? ffw : fbw) + ((size_t)t * B + b) * (size_t)N * 3;
            const float* tgt_fl = ((dir == 0) ? fbw : ffw) + ((size_t)t * B + b) * (size_t)N * 3;
            const float ox = src_fl[n * 3 + 0] + tgt_fl[idx * 3 + 0];
            const float oy = src_fl[n * 3 + 1] + tgt_fl[idx * 3 + 1];
            const float oz = src_fl[n * 3 + 2] + tgt_fl[idx * 3 + 2];
            v_opp = fmaf(ox, ox, fmaf(oy, oy, oz * oz));
        }
    }

    block_reduce2(v_nd2, v_opp, sA, sB);
    if (tid == 0) {
        g_nd2_part[combo * gridDim.x + blockIdx.x] = v_nd2;
        g_opp_part[combo * gridDim.x + blockIdx.x] = v_opp;
        __threadfence();
        const unsigned total = gridDim.x * gridDim.y;
        const unsigned old = atomicInc(&g_ctr, total - 1);   // wraps -> replay-safe
        isLast = (old == total - 1);
    }
    __syncthreads();
    if (!isLast) return;

    // ---- final fold (one block, 256 threads) ----
    const int BN = B * N;
    const int nbx2 = gridDim.x;
    float accA = 0.f, accB = 0.f;
    for (int i = tid; i < KC * nbx2; i += 256) {
        const int c  = i / nbx2;
        const int tt = (c / B) % T;
        const float wnd = (tt == 0) ? 0.5f : 0.25f;   // knn pens * 0.5 fw/bw avg
        float v = wnd * g_nd2_part[i];
        if (tt == 0) v += 0.5f * g_opp_part[i];
        accA += v;
    }
    for (int i = tid; i < 2 * nbx1; i += 256) {
        accA += 0.05f * g_occ_part[i] + 0.5f * g_sf_part[i];
    }
    for (int e = tid; e < B * 16; e += 256) {
        const int bbq = e >> 4, r = (e >> 2) & 3, k = e & 3;
        const float* A  = trfw + (size_t)bbq * 16;
        const float* Bm = trbw + (size_t)bbq * 16;
        float c = 0.f;
        #pragma unroll
        for (int j = 0; j < 4; j++) c = fmaf(A[r * 4 + j], Bm[j * 4 + k], c);
        const float d = c - ((r == k) ? 1.f : 0.f);
        accB += d * d;
    }
    __syncthreads();
    block_reduce2(accA, accB, sA, sB);
    if (tid == 0) out[0] = accA / (float)BN + accB / (float)B;
}

extern "C" void kernel_launch(void* const* d_in, const int* in_sizes, int n_in,
                              void* d_out, int out_size)
{
    const float* pc0  = (const float*)d_in[0];
    const float* pc1  = (const float*)d_in[1];
    const float* ffw  = (const float*)d_in[2];
    const float* fbw  = (const float*)d_in[3];
    const float* dfw  = (const float*)d_in[4];
    const float* dbw  = (const float*)d_in[5];
    const float* trfw = (const float*)d_in[6];
    const float* trbw = (const float*)d_in[7];
    const float* stfw = (const float*)d_in[8];
    const float* stbw = (const float*)d_in[9];
    float* out = (float*)d_out;

    const int B = in_sizes[6] / 16;                 // trafo_fw = [B,4,4]
    const int N = in_sizes[0] / (3 * B);            // pc0 = [B,N,3]
    const int T = in_sizes[2] / (3 * B * N);        // flows_fw = [T,B,N,3]

    const int KC  = 2 * T * B;
    const int nbx = (N + 255) / 256;                // 256 source points / block
    const int chunk = (N + JSPLIT - 1) / JSPLIT;

    dim3 grid1(nbx * JSPLIT, KC + 2);
    const size_t smem = (size_t)((chunk + 1) / 2) * 32;   // 2KB at N=2048
    chunk_kernel<<<grid1, 128, smem>>>(pc0, pc1, ffw, fbw, dfw, dbw,
                                       trfw, trbw, stfw, stbw, B, N, T);

    dim3 grid2((N + 255) / 256, KC);
    combine_kernel<<<grid2, 256>>>(ffw, fbw, trfw, trbw, out,
                                   B, N, T, nbx * JSPLIT);
}

// round 14
// speedup vs baseline: 2.7409x; 1.1098x over previous
#include <cuda_runtime.h>
#include <cuda_bf16.h>
#include <cstddef>

#define MAXC   16     // max combos (2*T*B <= 12 here)
#define JSPLIT 8      // target-dimension split
#define MAXN   4096   // max points
#define MAXP   128    // max partial blocks per row

// Packed per-point winner: ~(((u64)mono(d2) << 32) | idx), folded with
// atomicMax (no-return -> REDG). 0 = "empty"; combine reads + resets to 0.
__device__ unsigned long long g_slot[MAXC * MAXN];
__device__ float g_nd2_part[MAXC * MAXP];
__device__ float g_opp_part[MAXC * MAXP];
__device__ float g_occ_part[2 * MAXP];
__device__ float g_sf_part [2 * MAXP];
__device__ unsigned int g_ctr;                   // zero-init; wraps each launch

__device__ __forceinline__ unsigned int fkey(float f) {
    const unsigned int u = __float_as_uint(f);
    return u ^ ((u & 0x80000000u) ? 0xFFFFFFFFu : 0x80000000u);
}
__device__ __forceinline__ float fkey_inv(unsigned int k) {
    const unsigned int u = (k & 0x80000000u) ? (k ^ 0x80000000u) : ~k;
    return __uint_as_float(u);
}

// ---- packed f32x2 helpers (sm_103a FFMA2 path, PTX-only) ----
__device__ __forceinline__ unsigned long long pack2(float lo, float hi) {
    unsigned long long r;
    asm("mov.b64 %0, {%1, %2};" : "=l"(r) : "f"(lo), "f"(hi));
    return r;
}
__device__ __forceinline__ void unpack2(unsigned long long v, float& lo, float& hi) {
    asm("mov.b64 {%0, %1}, %2;" : "=f"(lo), "=f"(hi) : "l"(v));
}
__device__ __forceinline__ unsigned long long fma2(unsigned long long a,
                                                   unsigned long long b,
                                                   unsigned long long c) {
    unsigned long long d;
    asm("fma.rn.f32x2 %0, %1, %2, %3;" : "=l"(d) : "l"(a), "l"(b), "l"(c));
    return d;
}
__device__ __forceinline__ unsigned long long mul2(unsigned long long a,
                                                   unsigned long long b) {
    unsigned long long d;
    asm("mul.rn.f32x2 %0, %1, %2;" : "=l"(d) : "l"(a), "l"(b));
    return d;
}

__device__ __forceinline__ void block_reduce2(float& a, float& b,
                                              float* sA, float* sB) {
    const int lane = threadIdx.x & 31;
    const int wid  = threadIdx.x >> 5;
    #pragma unroll
    for (int off = 16; off > 0; off >>= 1) {
        a += __shfl_down_sync(0xffffffffu, a, off);
        b += __shfl_down_sync(0xffffffffu, b, off);
    }
    if (lane == 0) { sA[wid] = a; sB[wid] = b; }
    __syncthreads();
    if (threadIdx.x == 0) {
        const int nw = (blockDim.x + 31) >> 5;
        float ra = 0.f, rb = 0.f;
        for (int w = 0; w < nw; w++) { ra += sA[w]; rb += sB[w]; }
        a = ra; b = rb;
    }
}

// ---------------------------------------------------------------------------
// Pass 1: per-(combo, 256-pt block, 256-target chunk) partial NN folded into
// packed-key atomicMax. t==0 scalar argmin; t!=0 packed f32x2 FMA. Extras
// rows: occlusion + static-flow partials. Signals PDL dependents at the end.
// ---------------------------------------------------------------------------
__global__ void __launch_bounds__(128) chunk_kernel(
    const float* __restrict__ pc0, const float* __restrict__ pc1,
    const float* __restrict__ ffw, const float* __restrict__ fbw,
    const float* __restrict__ dfw, const float* __restrict__ dbw,
    const float* __restrict__ trfw, const float* __restrict__ trbw,
    const float* __restrict__ stfw, const float* __restrict__ stbw,
    int B, int N, int T)
{
    const int KC = 2 * T * B;
    const int combo = blockIdx.y;
    extern __shared__ unsigned long long smU[];
    float4* sm4 = reinterpret_cast<float4*>(smU);
    __shared__ float sA[8], sB[8];

    if (combo < KC) {
        const int b   = combo % B;
        const int t   = (combo / B) % T;
        const int dir = combo / (B * T);
        const int chunk = (N + JSPLIT - 1) / JSPLIT;
        const int xb = blockIdx.x / JSPLIT;
        const int jc = blockIdx.x % JSPLIT;
        const int j0 = jc * chunk;
        const int cnt = min(chunk, N - j0);
        if (cnt > 0) {

        const float* src_pc = (dir == 0) ? pc0 : pc1;
        const float* tgt_pc = (dir == 0) ? pc1 : pc0;
        const float* src_fl = (dir == 0) ? ffw : fbw;
        src_pc += (size_t)b * N * 3;
        tgt_pc += (size_t)b * N * 3;
        src_fl += ((size_t)t * B + b) * (size_t)N * 3;

        const int n0 = xb * 256 + (int)threadIdx.x;
        const int n1 = n0 + 128;
        const bool v0 = (n0 < N);
        const bool v1 = (n1 < N);

        float w0x = 0.f, w0y = 0.f, w0z = 0.f, w20 = 0.f;
        float w1x = 0.f, w1y = 0.f, w1z = 0.f, w21 = 0.f;
        if (v0) {
            w0x = src_pc[n0 * 3 + 0] + src_fl[n0 * 3 + 0];
            w0y = src_pc[n0 * 3 + 1] + src_fl[n0 * 3 + 1];
            w0z = src_pc[n0 * 3 + 2] + src_fl[n0 * 3 + 2];
            w20 = fmaf(w0x, w0x, fmaf(w0y, w0y, w0z * w0z));
        }
        if (v1) {
            w1x = src_pc[n1 * 3 + 0] + src_fl[n1 * 3 + 0];
            w1y = src_pc[n1 * 3 + 1] + src_fl[n1 * 3 + 1];
            w1z = src_pc[n1 * 3 + 2] + src_fl[n1 * 3 + 2];
            w21 = fmaf(w1x, w1x, fmaf(w1y, w1y, w1z * w1z));
        }

        unsigned long long* slot = g_slot + (size_t)combo * N;

        if (t == 0) {
            // ---------- scalar argmin path ----------
            for (int i = threadIdx.x; i < cnt; i += 128) {
                const float ax = tgt_pc[(j0 + i) * 3 + 0];
                const float ay = tgt_pc[(j0 + i) * 3 + 1];
                const float az = tgt_pc[(j0 + i) * 3 + 2];
                sm4[i] = make_float4(ax, ay, az, fmaf(ax, ax, fmaf(ay, ay, az * az)));
            }
            __syncthreads();

            float best0 = 3.402823466e+38f, best1 = 3.402823466e+38f;
            int   bi0 = 0, bi1 = 0;
            #pragma unroll 4
            for (int j = 0; j < cnt; j++) {
                const float4 a = sm4[j];
                const float s0 = fmaf(fmaf(a.x, w0x, fmaf(a.y, w0y, a.z * w0z)), -2.f, a.w);
                if (s0 < best0) { best0 = s0; bi0 = j; }
                const float s1 = fmaf(fmaf(a.x, w1x, fmaf(a.y, w1y, a.z * w1z)), -2.f, a.w);
                if (s1 < best1) { best1 = s1; bi1 = j; }
            }
            if (v0) {
                const unsigned long long key =
                    ((unsigned long long)fkey(best0 + w20) << 32) | (unsigned int)(j0 + bi0);
                atomicMax(slot + n0, ~key);
            }
            if (v1) {
                const unsigned long long key =
                    ((unsigned long long)fkey(best1 + w21) << 32) | (unsigned int)(j0 + bi1);
                atomicMax(slot + n1, ~key);
            }
        } else {
            // ---------- packed f32x2 min-only path ----------
            const int cnt2 = (cnt + 1) >> 1;
            for (int i = threadIdx.x; i < cnt2; i += 128) {
                const int ta = j0 + 2 * i;
                const int tb = ta + 1;
                const float ax0 = tgt_pc[ta * 3 + 0];
                const float ay0 = tgt_pc[ta * 3 + 1];
                const float az0 = tgt_pc[ta * 3 + 2];
                const float aw0 = fmaf(ax0, ax0, fmaf(ay0, ay0, az0 * az0));
                float ax1 = 0.f, ay1 = 0.f, az1 = 0.f, aw1 = 3.402823466e+38f;
                if (tb < j0 + cnt) {
                    ax1 = tgt_pc[tb * 3 + 0];
                    ay1 = tgt_pc[tb * 3 + 1];
                    az1 = tgt_pc[tb * 3 + 2];
                    aw1 = fmaf(ax1, ax1, fmaf(ay1, ay1, az1 * az1));
                }
                smU[i * 4 + 0] = pack2(ax0, ax1);
                smU[i * 4 + 1] = pack2(ay0, ay1);
                smU[i * 4 + 2] = pack2(az0, az1);
                smU[i * 4 + 3] = pack2(aw0, aw1);
            }
            __syncthreads();

            const unsigned long long X0 = pack2(w0x, w0x), Y0 = pack2(w0y, w0y), Z0 = pack2(w0z, w0z);
            const unsigned long long X1 = pack2(w1x, w1x), Y1 = pack2(w1y, w1y), Z1 = pack2(w1z, w1z);
            const unsigned long long NEG2 = pack2(-2.f, -2.f);

            float bE0 = 3.402823466e+38f, bO0 = 3.402823466e+38f;
            float bE1 = 3.402823466e+38f, bO1 = 3.402823466e+38f;
            #pragma unroll 8
            for (int j2 = 0; j2 < cnt2; j2++) {
                const ulonglong2 pxy = *reinterpret_cast<const ulonglong2*>(&smU[j2 * 4]);
                const ulonglong2 pzw = *reinterpret_cast<const ulonglong2*>(&smU[j2 * 4 + 2]);
                unsigned long long s = fma2(fma2(pxy.x, X0, fma2(pxy.y, Y0, mul2(pzw.x, Z0))), NEG2, pzw.y);
                float lo, hi; unpack2(s, lo, hi);
                bE0 = fminf(bE0, lo); bO0 = fminf(bO0, hi);
                s = fma2(fma2(pxy.x, X1, fma2(pxy.y, Y1, mul2(pzw.x, Z1))), NEG2, pzw.y);
                unpack2(s, lo, hi);
                bE1 = fminf(bE1, lo); bO1 = fminf(bO1, hi);
            }
            const float best0 = fminf(bE0, bO0);
            const float best1 = fminf(bE1, bO1);
            if (v0) atomicMax(slot + n0, ~((unsigned long long)fkey(best0 + w20) << 32));
            if (v1) atomicMax(slot + n1, ~((unsigned long long)fkey(best1 + w21) << 32));
        }
        }
    } else {
        // ---- extras: occlusion + static-flow partials ----
        const int dir = combo - KC;
        const float* pc  = (dir == 0) ? pc0  : pc1;
        const float* fl  = (dir == 0) ? ffw  : fbw;
        const float* dis = (dir == 0) ? dfw  : dbw;
        const float* st  = (dir == 0) ? stfw : stbw;
        const float* trg = (dir == 0) ? trfw : trbw;
        const int BN = B * N;
        fl += (size_t)2 * BN * 3;

        float occ = 0.f, sf = 0.f;
        for (int i = blockIdx.x * 128 + (int)threadIdx.x; i < BN;
             i += gridDim.x * 128) {
            occ += dis[i];
            const int b = i / N;
            const float* m = trg + (size_t)b * 16;
            const float px = pc[i * 3 + 0], py = pc[i * 3 + 1], pz = pc[i * 3 + 2];
            const float ix = fmaf(m[0], px, fmaf(m[1],  py, fmaf(m[2],  pz, m[3])))  - px;
            const float iy = fmaf(m[4], px, fmaf(m[5],  py, fmaf(m[6],  pz, m[7])))  - py;
            const float iz = fmaf(m[8], px, fmaf(m[9],  py, fmaf(m[10], pz, m[11]))) - pz;
            const float* f = fl + (size_t)i * 3;
            const float dx = f[0] - ix, dy = f[1] - iy, dz = f[2] - iz;
            sf += st[i] * fmaf(dx, dx, fmaf(dy, dy, dz * dz));
        }
        block_reduce2(occ, sf, sA, sB);
        if (threadIdx.x == 0) {
            g_occ_part[dir * gridDim.x + blockIdx.x] = occ;
            g_sf_part [dir * gridDim.x + blockIdx.x] = sf;
        }
    }

    // Allow the dependent (combine) grid to launch and run its prologue.
    asm volatile("griddepcontrol.launch_dependents;");
}

// ---------------------------------------------------------------------------
// Pass 2 (PDL dependent): prologue computes addressing, then waits for the
// primary grid (full completion + visibility), then reads/decodes winners.
// Last-arriving block folds partials + extras + trafo loss -> out[0].
// ---------------------------------------------------------------------------
__global__ void __launch_bounds__(256) combine_kernel(
    const float* __restrict__ ffw, const float* __restrict__ fbw,
    const float* __restrict__ trfw, const float* __restrict__ trbw,
    float* __restrict__ out, int B, int N, int T, int nbx1)
{
    const int combo = blockIdx.y;
    const int b   = combo % B;
    const int t   = (combo / B) % T;
    const int dir = combo / (B * T);
    const int KC  = 2 * T * B;
    const int tid = threadIdx.x;
    __shared__ float sA[8], sB[8];
    __shared__ bool isLast;

    const int n = blockIdx.x * 256 + tid;
    unsigned long long* slot = g_slot + (size_t)combo * N + n;
    const float* src_fl = ((dir == 0) ? ffw : fbw) + (size_t)b * N * 3;  // t==0 slice
    const float* tgt_fl = ((dir == 0) ? fbw : ffw) + (size_t)b * N * 3;

    // Wait for the primary grid's results to be complete & visible.
    asm volatile("griddepcontrol.wait;" ::: "memory");

    float v_nd2 = 0.f, v_opp = 0.f;
    if (n < N) {
        const unsigned long long key = ~(*slot);
        *slot = 0ULL;                                   // reset for next replay
        const float d2 = fkey_inv((unsigned int)(key >> 32));
        v_nd2 = fmaxf(d2, 0.f);
        if (t == 0) {
            const int idx = (int)(unsigned int)(key & 0xFFFFFFFFu);
            const float ox = src_fl[n * 3 + 0] + tgt_fl[idx * 3 + 0];
            const float oy = src_fl[n * 3 + 1] + tgt_fl[idx * 3 + 1];
            const float oz = src_fl[n * 3 + 2] + tgt_fl[idx * 3 + 2];
            v_opp = fmaf(ox, ox, fmaf(oy, oy, oz * oz));
        }
    }

    block_reduce2(v_nd2, v_opp, sA, sB);
    if (tid == 0) {
        g_nd2_part[combo * gridDim.x + blockIdx.x] = v_nd2;
        g_opp_part[combo * gridDim.x + blockIdx.x] = v_opp;
        __threadfence();
        const unsigned total = gridDim.x * gridDim.y;
        const unsigned old = atomicInc(&g_ctr, total - 1);   // wraps -> replay-safe
        isLast = (old == total - 1);
    }
    __syncthreads();
    if (!isLast) return;

    // ---- final fold (one block, 256 threads) ----
    const int BN = B * N;
    const int nbx2 = gridDim.x;
    float accA = 0.f, accB = 0.f;
    for (int i = tid; i < KC * nbx2; i += 256) {
        const int c  = i / nbx2;
        const int tt = (c / B) % T;
        const float wnd = (tt == 0) ? 0.5f : 0.25f;   // knn pens * 0.5 fw/bw avg
        float v = wnd * g_nd2_part[i];
        if (tt == 0) v += 0.5f * g_opp_part[i];
        accA += v;
    }
    for (int i = tid; i < 2 * nbx1; i += 256) {
        accA += 0.05f * g_occ_part[i] + 0.5f * g_sf_part[i];
    }
    for (int e = tid; e < B * 16; e += 256) {
        const int bbq = e >> 4, r = (e >> 2) & 3, k = e & 3;
        const float* A  = trfw + (size_t)bbq * 16;
        const float* Bm = trbw + (size_t)bbq * 16;
        float c = 0.f;
        #pragma unroll
        for (int j = 0; j < 4; j++) c = fmaf(A[r * 4 + j], Bm[j * 4 + k], c);
        const float d = c - ((r == k) ? 1.f : 0.f);
        accB += d * d;
    }
    __syncthreads();
    block_reduce2(accA, accB, sA, sB);
    if (tid == 0) out[0] = accA / (float)BN + accB / (float)B;
}

extern "C" void kernel_launch(void* const* d_in, const int* in_sizes, int n_in,
                              void* d_out, int out_size)
{
    const float* pc0  = (const float*)d_in[0];
    const float* pc1  = (const float*)d_in[1];
    const float* ffw  = (const float*)d_in[2];
    const float* fbw  = (const float*)d_in[3];
    const float* dfw  = (const float*)d_in[4];
    const float* dbw  = (const float*)d_in[5];
    const float* trfw = (const float*)d_in[6];
    const float* trbw = (const float*)d_in[7];
    const float* stfw = (const float*)d_in[8];
    const float* stbw = (const float*)d_in[9];
    float* out = (float*)d_out;

    const int B = in_sizes[6] / 16;                 // trafo_fw = [B,4,4]
    const int N = in_sizes[0] / (3 * B);            // pc0 = [B,N,3]
    const int T = in_sizes[2] / (3 * B * N);        // flows_fw = [T,B,N,3]

    const int KC  = 2 * T * B;
    const int nbx = (N + 255) / 256;                // 256 source points / block
    const int chunk = (N + JSPLIT - 1) / JSPLIT;

    dim3 grid1(nbx * JSPLIT, KC + 2);
    const size_t smem = (size_t)((chunk + 1) / 2) * 32;   // 4KB at N=2048
    chunk_kernel<<<grid1, 128, smem>>>(pc0, pc1, ffw, fbw, dfw, dbw,
                                       trfw, trbw, stfw, stbw, B, N, T);

    // Dependent launch with programmatic stream serialization (PDL overlap).
    dim3 grid2((N + 255) / 256, KC);
    cudaLaunchConfig_t cfg = {};
    cfg.gridDim = grid2;
    cfg.blockDim = dim3(256, 1, 1);
    cfg.dynamicSmemBytes = 0;
    cfg.stream = 0;
    cudaLaunchAttribute attrs[1];
    attrs[0].id = cudaLaunchAttributeProgrammaticStreamSerialization;
    attrs[0].val.programmaticStreamSerializationAllowed = 1;
    cfg.attrs = attrs;
    cfg.numAttrs = 1;
    cudaLaunchKernelEx(&cfg, combine_kernel, ffw, fbw, trfw, trbw, out,
                       B, N, T, nbx * JSPLIT);
}